// round 14
// baseline (speedup 1.0000x reference)
#include <cuda_runtime.h>
#include <cuda_fp16.h>
#include <cstdint>
#include <cstddef>
#include <math.h>

#define B 4
#define L 256
#define D 512
#define O 128
#define BX 1024
#define WSTRIDE 263169       // 513*513
#define WSCALE 256.0f
#define INV_WSCALE (1.0f/256.0f)

// ---------------- device scratch (static, no runtime alloc) ----------------
__device__ __half g_x1h[BX * D];
__device__ __half g_x2h[BX * D];
__device__ __half g_Wh[(size_t)O * D * D];   // 256*Wt[o][j][i]
__device__ __half g_Th[(size_t)BX * O * D];  // 256*T[bx][o][j]
__device__ __half g_WcH[2 * O * D];          // 256*Wc[which][o][d]
__device__ float g_bias[2 * O];
__device__ float g_A1[BX * O];
__device__ float g_A2[BX * O];

// ---------------- low-level helpers ----------------
__device__ __forceinline__ uint32_t s2u(const void* p) {
    uint32_t a;
    asm("{ .reg .u64 t; cvta.to.shared.u64 t, %1; cvt.u32.u64 %0, t; }" : "=r"(a) : "l"(p));
    return a;
}
__device__ __forceinline__ void cpa16(uint32_t d, const void* s) {
    asm volatile("cp.async.cg.shared.global [%0], [%1], 16;" :: "r"(d), "l"(s) : "memory");
}
#define CP_COMMIT() asm volatile("cp.async.commit_group;" ::: "memory")

__device__ __forceinline__ void ldsm_x4(uint32_t a, uint32_t r[4]) {
    asm volatile("ldmatrix.sync.aligned.m8n8.x4.shared.b16 {%0,%1,%2,%3}, [%4];"
                 : "=r"(r[0]), "=r"(r[1]), "=r"(r[2]), "=r"(r[3]) : "r"(a));
}
__device__ __forceinline__ void mma16816(float c[4], const uint32_t a[4], const uint32_t b[2]) {
    asm volatile(
        "mma.sync.aligned.m16n8k16.row.col.f32.f16.f16.f32 "
        "{%0,%1,%2,%3}, {%4,%5,%6,%7}, {%8,%9}, {%0,%1,%2,%3};"
        : "+f"(c[0]), "+f"(c[1]), "+f"(c[2]), "+f"(c[3])
        : "r"(a[0]), "r"(a[1]), "r"(a[2]), "r"(a[3]), "r"(b[0]), "r"(b[1]));
}

// ---- tiles per BK=64 chunk: plane = 128 rows x 64 fp16 (128B) + 16B pad -> 144B stride
#define PLANE_B  18432      // 128*144
#define STAGE_B  36864      // A plane + B plane
#define NSTAGE   3
#define GSMEM    110592     // 3 stages -> occ 2

// 128 threads: load one stage (A plane + B plane); gmem row stride 512 elems
__device__ __forceinline__ void load_stage(uint32_t sb, int s,
    const __half* Ah, const __half* Bh, int tid, int k0)
{
    const uint32_t st = sb + s * STAGE_B;
    #pragma unroll
    for (int it = 0; it < 8; it++) {
        const int op = it * 128 + tid;          // 0..1023
        const int r = op >> 3, ch = op & 7;
        const size_t goff = (size_t)r * 1024 + (size_t)k0 * 2 + ch * 16;
        cpa16(st + r * 144 + ch * 16, (const char*)Ah + goff);
        cpa16(st + PLANE_B + r * 144 + ch * 16, (const char*)Bh + goff);
    }
}

// 64x64 warp tile: acc[4 mt][8 nt][4]
__device__ __forceinline__ void compute_k16(uint32_t base, int kk, int lane,
                                            int warp_m, int warp_n, float acc[4][8][4]) {
    uint32_t ah[4][4];
    const int cola = kk + (lane >> 4) * 8;
    #pragma unroll
    for (int mt = 0; mt < 4; mt++) {
        const int row = warp_m * 64 + mt * 16 + (lane & 7) + ((lane >> 3) & 1) * 8;
        ldsm_x4(base + row * 144 + cola * 2, ah[mt]);
    }
    uint32_t bh[4][4];
    const int colb = kk + ((lane >> 3) & 1) * 8;
    #pragma unroll
    for (int p = 0; p < 4; p++) {
        const int n = warp_n * 64 + p * 16 + (lane & 7) + (lane >> 4) * 8;
        ldsm_x4(base + PLANE_B + n * 144 + colb * 2, bh[p]);
    }
    #pragma unroll
    for (int mt = 0; mt < 4; mt++)
        #pragma unroll
        for (int nt = 0; nt < 8; nt++)
            mma16816(acc[mt][nt], ah[mt], &bh[nt >> 1][(nt & 1) * 2]);
}

// C[128x128] += A*B^T over K=512; BK=64, 3-stage pipeline, 4 warps (2x2)
__device__ __forceinline__ void gemm_loop(uint32_t sb, int tid,
    const __half* Ah, const __half* Bh, float acc[4][8][4])
{
    const int lane = tid & 31;
    const int warp = tid >> 5;
    const int warp_m = warp >> 1, warp_n = warp & 1;

    load_stage(sb, 0, Ah, Bh, tid, 0);  CP_COMMIT();
    load_stage(sb, 1, Ah, Bh, tid, 64); CP_COMMIT();

    int s_c = 0, s_n = 2;
    #pragma unroll 1
    for (int c = 0; c < 8; c++) {
        if (c + 1 < 8) asm volatile("cp.async.wait_group 1;" ::: "memory");
        else           asm volatile("cp.async.wait_group 0;" ::: "memory");
        __syncthreads();
        if (c + 2 < 8) {
            load_stage(sb, s_n, Ah, Bh, tid, (c + 2) * 64);
            CP_COMMIT();
            if (++s_n == NSTAGE) s_n = 0;
        }
        const uint32_t base = sb + s_c * STAGE_B;
        compute_k16(base, 0,  lane, warp_m, warp_n, acc);
        compute_k16(base, 16, lane, warp_m, warp_n, acc);
        compute_k16(base, 32, lane, warp_m, warp_n, acc);
        compute_k16(base, 48, lane, warp_m, warp_n, acc);
        if (++s_c == NSTAGE) s_c = 0;
    }
    __syncthreads();   // protect smem reuse by epilogues
}

// ---------------- pre-pass kernels ----------------
__global__ __launch_bounds__(256)
void prep_x(const float* __restrict__ x1, const float* __restrict__ x2)
{
    int i = blockIdx.x * 256 + threadIdx.x;
    if (i >= BX * D) return;
    g_x1h[i] = __float2half_rn(x1[i]);
    g_x2h[i] = __float2half_rn(x2[i]);
}

// Transpose 256*W core for o in [o0, o0+64)
__global__ __launch_bounds__(256)
void prep_w(const float* __restrict__ W, int o0)
{
    const int o  = o0 + blockIdx.z;
    const int i0 = blockIdx.y * 64, j0 = blockIdx.x * 32;
    __shared__ float t[64][33];
    const int tid = threadIdx.x;
    const float* Wo = W + (size_t)o * WSTRIDE;

    #pragma unroll
    for (int p = 0; p < 8; p++) {
        int idx = p * 256 + tid;
        int i = idx >> 5, j = idx & 31;
        t[i][j] = Wo[(size_t)(i0 + i) * 513 + (j0 + j)] * WSCALE;
    }
    __syncthreads();

    const size_t ob = (size_t)o * D * D;
    #pragma unroll
    for (int p = 0; p < 4; p++) {
        const int jl = p * 8 + (tid >> 5);
        const int i2 = (tid & 31) * 2;
        const size_t off = ob + (size_t)(j0 + jl) * D + i0 + i2;
        *reinterpret_cast<__half2*>(g_Wh + off) =
            __halves2half2(__float2half_rn(t[i2][jl]), __float2half_rn(t[i2 + 1][jl]));
    }
}

__global__ __launch_bounds__(256)
void comb_w(const float* __restrict__ W, const float* __restrict__ Wlin,
            const float* __restrict__ b_lin, const float* __restrict__ bw)
{
    const int idx = blockIdx.x * 256 + threadIdx.x;
    if (idx >= 2 * O * D) return;
    const float e0 = expf(bw[0]), e1 = expf(bw[1]);
    const float w0 = e0 / (e0 + e1), w1 = e1 / (e0 + e1);

    const int d = idx & 511;
    const int o = (idx >> 9) & 127;
    const int which = idx >> 16;
    const float we = which ? W[(size_t)o * WSTRIDE + (size_t)512 * 513 + d]
                           : W[(size_t)o * WSTRIDE + (size_t)d * 513 + 512];
    const float wl = Wlin[(size_t)(which * D + d) * O + o];
    g_WcH[idx] = __float2half_rn((w0 * we + w1 * wl) * WSCALE);

    if (idx < O)          g_bias[idx] = w1 * b_lin[idx];
    else if (idx < 2 * O) {
        const int oo = idx - O;
        g_bias[idx] = w0 * W[(size_t)oo * WSTRIDE + (size_t)512 * 513 + 512];
    }
}

// A-terms: A{1,2}[m,o] = (x @ Wc^T)/256 + bias  (4 warps)
__global__ __launch_bounds__(128, 2)
void A_terms_mma()
{
    extern __shared__ char smem[];
    const uint32_t sb = s2u(smem);
    const int tid = threadIdx.x;
    const int m0 = blockIdx.x * 128;
    const int which = blockIdx.y;

    const __half* Ah = (which ? g_x2h : g_x1h) + (size_t)m0 * D;
    const __half* Bh = g_WcH + (size_t)which * O * D;

    float acc[4][8][4] = {};
    gemm_loop(sb, tid, Ah, Bh, acc);

    float* dst = which ? g_A2 : g_A1;
    const float* bias = g_bias + which * O;
    const int lane = tid & 31, warp = tid >> 5;
    const int warp_m = warp >> 1, warp_n = warp & 1;
    #pragma unroll
    for (int mt = 0; mt < 4; mt++)
        #pragma unroll
        for (int nt = 0; nt < 8; nt++) {
            const int oc = warp_n * 64 + nt * 8 + (lane & 3) * 2;
            const float b0 = bias[oc], b1 = bias[oc + 1];
            #pragma unroll
            for (int h = 0; h < 2; h++) {
                const int m = m0 + warp_m * 64 + mt * 16 + (lane >> 2) + h * 8;
                *reinterpret_cast<float2*>(dst + (size_t)m * O + oc) =
                    make_float2(fmaf(acc[mt][nt][h * 2],     INV_WSCALE, b0),
                                fmaf(acc[mt][nt][h * 2 + 1], INV_WSCALE, b1));
            }
        }
}

// ---------------- stage 1 (o-half): T[m, o, j] for o in [o0, o0+64) --------
#define S1_PITCH 272
__global__ __launch_bounds__(128, 2)
void stage1_mma(int o0)
{
    extern __shared__ char smem[];
    const uint32_t sb = s2u(smem);
    const int tid = threadIdx.x;
    const int m0 = blockIdx.x * 128;
    const int o  = o0 + (blockIdx.y >> 2);
    const int j0 = (blockIdx.y & 3) * 128;

    float acc[4][8][4] = {};
    gemm_loop(sb, tid,
              g_x1h + (size_t)m0 * D,
              g_Wh + (size_t)o * D * D + (size_t)j0 * D, acc);

    const int lane = tid & 31, warp = tid >> 5;
    const int warp_m = warp >> 1, warp_n = warp & 1;
    #pragma unroll
    for (int mt = 0; mt < 4; mt++)
        #pragma unroll
        for (int nt = 0; nt < 8; nt++)
            #pragma unroll
            for (int h = 0; h < 2; h++) {
                const int ml = warp_m * 64 + mt * 16 + (lane >> 2) + h * 8;
                const int jl = warp_n * 64 + nt * 8 + (lane & 3) * 2;
                *reinterpret_cast<__half2*>(smem + ml * S1_PITCH + jl * 2) =
                    __halves2half2(__float2half_rn(acc[mt][nt][h * 2]),
                                   __float2half_rn(acc[mt][nt][h * 2 + 1]));
            }
    __syncthreads();

    #pragma unroll
    for (int p = 0; p < 16; p++) {
        const int q = p * 128 + tid;
        const int r = q >> 4, c = q & 15;
        const size_t go = ((size_t)(m0 + r) * O + o) * D + j0 + c * 8;
        *reinterpret_cast<uint4*>(g_Th + go) =
            *reinterpret_cast<uint4*>(smem + r * S1_PITCH + c * 16);
    }
}

// ---------------- stage 2: out = (w0/256) * x2 . (256*T[bx]) + A1 + A2 -----
#define S2_PITCH 528
__global__ __launch_bounds__(128, 2)
void stage2_mma(const float* __restrict__ bw, float* __restrict__ out)
{
    extern __shared__ char smem[];
    const uint32_t sb = s2u(smem);
    const int tid = threadIdx.x;
    const int y0 = blockIdx.x * 128;
    const int bx = blockIdx.y;
    const int b  = bx >> 8;
    const size_t arow = (size_t)(b * L + y0) * D;

    float acc[4][8][4] = {};
    gemm_loop(sb, tid,
              g_x2h + arow,
              g_Th + (size_t)bx * O * D, acc);

    const int lane = tid & 31, warp = tid >> 5;
    const int warp_m = warp >> 1, warp_n = warp & 1;
    #pragma unroll
    for (int mt = 0; mt < 4; mt++)
        #pragma unroll
        for (int nt = 0; nt < 8; nt++)
            #pragma unroll
            for (int h = 0; h < 2; h++) {
                const int yl = warp_m * 64 + mt * 16 + (lane >> 2) + h * 8;
                const int ol = warp_n * 64 + nt * 8 + (lane & 3) * 2;
                *reinterpret_cast<float2*>(smem + yl * S2_PITCH + ol * 4) =
                    make_float2(acc[mt][nt][h * 2], acc[mt][nt][h * 2 + 1]);
            }
    __syncthreads();

    const float e0 = expf(bw[0]), e1 = expf(bw[1]);
    const float w0s = (e0 / (e0 + e1)) * INV_WSCALE;

    #pragma unroll
    for (int p = 0; p < 32; p++) {
        const int q = p * 128 + tid;
        const int r = q >> 5, c = q & 31;
        const float4 v = *reinterpret_cast<float4*>(smem + r * S2_PITCH + c * 16);
        const float4 a1 = *reinterpret_cast<const float4*>(g_A1 + (size_t)bx * O + c * 4);
        const float4 a2 = *reinterpret_cast<const float4*>(g_A2 + (size_t)(b * L + y0 + r) * O + c * 4);
        float4 rr;
        rr.x = fmaf(w0s, v.x, a1.x + a2.x);
        rr.y = fmaf(w0s, v.y, a1.y + a2.y);
        rr.z = fmaf(w0s, v.z, a1.z + a2.z);
        rr.w = fmaf(w0s, v.w, a1.w + a2.w);
        *reinterpret_cast<float4*>(out + ((size_t)bx * L + y0 + r) * O + c * 4) = rr;
    }
}

// ---------------------------------------------------------------------------
extern "C" void kernel_launch(void* const* d_in, const int* in_sizes, int n_in,
                              void* d_out, int out_size)
{
    const float* x1    = (const float*)d_in[0];
    const float* x2    = (const float*)d_in[1];
    const float* bw    = (const float*)d_in[2];
    const float* W_bil = (const float*)d_in[3];
    const float* W_lin = (const float*)d_in[4];
    const float* b_lin = (const float*)d_in[5];
    float* out = (float*)d_out;

    static cudaStream_t s1 = nullptr, s2 = nullptr, s3 = nullptr;
    static cudaEvent_t evRoot, evX, ev1, ev2, ev3;
    if (s1 == nullptr) {
        cudaStreamCreateWithFlags(&s1, cudaStreamNonBlocking);
        cudaStreamCreateWithFlags(&s2, cudaStreamNonBlocking);
        cudaStreamCreateWithFlags(&s3, cudaStreamNonBlocking);
        cudaEventCreateWithFlags(&evRoot, cudaEventDisableTiming);
        cudaEventCreateWithFlags(&evX,    cudaEventDisableTiming);
        cudaEventCreateWithFlags(&ev1,    cudaEventDisableTiming);
        cudaEventCreateWithFlags(&ev2,    cudaEventDisableTiming);
        cudaEventCreateWithFlags(&ev3,    cudaEventDisableTiming);
        cudaFuncSetAttribute(A_terms_mma, cudaFuncAttributeMaxDynamicSharedMemorySize, GSMEM);
        cudaFuncSetAttribute(stage1_mma,  cudaFuncAttributeMaxDynamicSharedMemorySize, GSMEM);
        cudaFuncSetAttribute(stage2_mma,  cudaFuncAttributeMaxDynamicSharedMemorySize, GSMEM);
    }

    cudaEventRecord(evRoot, 0);
    cudaStreamWaitEvent(s1, evRoot, 0);
    cudaStreamWaitEvent(s2, evRoot, 0);
    cudaStreamWaitEvent(s3, evRoot, 0);

    prep_w<<<dim3(16, 8, 64), 256, 0, s1>>>(W_bil, 0);
    prep_w<<<dim3(16, 8, 64), 256, 0, s2>>>(W_bil, 64);

    prep_x<<<(BX * D + 255) / 256, 256>>>(x1, x2);
    cudaEventRecord(evX, 0);

    cudaStreamWaitEvent(s3, evX, 0);
    comb_w<<<(2 * O * D + 255) / 256, 256, 0, s3>>>(W_bil, W_lin, b_lin, bw);
    A_terms_mma<<<dim3(8, 2), 128, GSMEM, s3>>>();
    cudaEventRecord(ev3, s3);

    cudaStreamWaitEvent(s1, evX, 0);
    stage1_mma<<<dim3(8, 256), 128, GSMEM, s1>>>(0);
    cudaEventRecord(ev1, s1);

    cudaStreamWaitEvent(s2, evX, 0);
    stage1_mma<<<dim3(8, 256), 128, GSMEM, s2>>>(64);
    cudaEventRecord(ev2, s2);

    cudaStreamWaitEvent(0, ev1, 0);
    cudaStreamWaitEvent(0, ev2, 0);
    cudaStreamWaitEvent(0, ev3, 0);
    stage2_mma<<<dim3(2, BX), 128, GSMEM>>>(bw, out);
}

// round 15
// speedup vs baseline: 1.0457x; 1.0457x over previous
#include <cuda_runtime.h>
#include <cuda_fp16.h>
#include <cstdint>
#include <cstddef>
#include <math.h>

#define B 4
#define L 256
#define D 512
#define O 128
#define BX 1024
#define WSTRIDE 263169       // 513*513
#define WSCALE 256.0f
#define INV_WSCALE (1.0f/256.0f)

// ---------------- device scratch (static, no runtime alloc) ----------------
__device__ __half g_x1h[BX * D];
__device__ __half g_x2h[BX * D];
__device__ __half g_Wh[(size_t)O * D * D];   // 256*Wt[o][j][i]
__device__ __half g_Th[(size_t)BX * O * D];  // 256*T[bx][o][j]
__device__ __half g_WcH[2 * O * D];          // 256*Wc[which][o][d]
__device__ float g_bias[2 * O];
__device__ float g_A1[BX * O];
__device__ float g_A2[BX * O];

// ---------------- low-level helpers ----------------
__device__ __forceinline__ uint32_t s2u(const void* p) {
    uint32_t a;
    asm("{ .reg .u64 t; cvta.to.shared.u64 t, %1; cvt.u32.u64 %0, t; }" : "=r"(a) : "l"(p));
    return a;
}
__device__ __forceinline__ void cpa16(uint32_t d, const void* s) {
    asm volatile("cp.async.cg.shared.global [%0], [%1], 16;" :: "r"(d), "l"(s) : "memory");
}
#define CP_COMMIT() asm volatile("cp.async.commit_group;" ::: "memory")

__device__ __forceinline__ void ldsm_x4(uint32_t a, uint32_t r[4]) {
    asm volatile("ldmatrix.sync.aligned.m8n8.x4.shared.b16 {%0,%1,%2,%3}, [%4];"
                 : "=r"(r[0]), "=r"(r[1]), "=r"(r[2]), "=r"(r[3]) : "r"(a));
}
__device__ __forceinline__ void mma16816(float c[4], const uint32_t a[4], const uint32_t b[2]) {
    asm volatile(
        "mma.sync.aligned.m16n8k16.row.col.f32.f16.f16.f32 "
        "{%0,%1,%2,%3}, {%4,%5,%6,%7}, {%8,%9}, {%0,%1,%2,%3};"
        : "+f"(c[0]), "+f"(c[1]), "+f"(c[2]), "+f"(c[3])
        : "r"(a[0]), "r"(a[1]), "r"(a[2]), "r"(a[3]), "r"(b[0]), "r"(b[1]));
}

// ---- tiles per BK=64 chunk: plane = 128 rows x 64 fp16 (128B) + 16B pad -> 144B stride
#define PLANE_B  18432      // 128*144
#define STAGE_B  36864      // A plane + B plane
#define NSTAGE   3
#define GSMEM    110592     // 3 stages -> occ 2

// 256 threads: load one stage (A plane + B plane); gmem row stride 512 elems
__device__ __forceinline__ void load_stage(uint32_t sb, int s,
    const __half* Ah, const __half* Bh, int tid, int k0)
{
    const uint32_t st = sb + s * STAGE_B;
    #pragma unroll
    for (int it = 0; it < 4; it++) {
        const int op = it * 256 + tid;          // 0..1023
        const int r = op >> 3, ch = op & 7;
        const size_t goff = (size_t)r * 1024 + (size_t)k0 * 2 + ch * 16;
        cpa16(st + r * 144 + ch * 16, (const char*)Ah + goff);
        cpa16(st + PLANE_B + r * 144 + ch * 16, (const char*)Bh + goff);
    }
}

__device__ __forceinline__ void compute_k16(uint32_t base, int kk, int lane,
                                            int warp_m, int warp_n, float acc[4][4][4]) {
    uint32_t ah[4][4];
    const int cola = kk + (lane >> 4) * 8;
    #pragma unroll
    for (int mt = 0; mt < 4; mt++) {
        const int row = warp_m * 64 + mt * 16 + (lane & 7) + ((lane >> 3) & 1) * 8;
        ldsm_x4(base + row * 144 + cola * 2, ah[mt]);
    }
    uint32_t bh[2][4];
    const int colb = kk + ((lane >> 3) & 1) * 8;
    #pragma unroll
    for (int p = 0; p < 2; p++) {
        const int n = warp_n * 32 + p * 16 + (lane & 7) + (lane >> 4) * 8;
        ldsm_x4(base + PLANE_B + n * 144 + colb * 2, bh[p]);
    }
    #pragma unroll
    for (int mt = 0; mt < 4; mt++)
        #pragma unroll
        for (int nt = 0; nt < 4; nt++)
            mma16816(acc[mt][nt], ah[mt], &bh[nt >> 1][(nt & 1) * 2]);
}

// C[128x128] += A*B^T over K=512; BK=64, 3-stage pipeline, 8 warps (2x4)
__device__ __forceinline__ void gemm_loop(uint32_t sb, int tid,
    const __half* Ah, const __half* Bh, float acc[4][4][4])
{
    const int lane = tid & 31;
    const int warp_m = (tid >> 5) & 1, warp_n = tid >> 6;

    load_stage(sb, 0, Ah, Bh, tid, 0);  CP_COMMIT();
    load_stage(sb, 1, Ah, Bh, tid, 64); CP_COMMIT();

    int s_c = 0, s_n = 2;
    #pragma unroll 1
    for (int c = 0; c < 8; c++) {
        if (c + 1 < 8) asm volatile("cp.async.wait_group 1;" ::: "memory");
        else           asm volatile("cp.async.wait_group 0;" ::: "memory");
        __syncthreads();
        if (c + 2 < 8) {
            load_stage(sb, s_n, Ah, Bh, tid, (c + 2) * 64);
            CP_COMMIT();
            if (++s_n == NSTAGE) s_n = 0;
        }
        const uint32_t base = sb + s_c * STAGE_B;
        compute_k16(base, 0,  lane, warp_m, warp_n, acc);
        compute_k16(base, 16, lane, warp_m, warp_n, acc);
        compute_k16(base, 32, lane, warp_m, warp_n, acc);
        compute_k16(base, 48, lane, warp_m, warp_n, acc);
        if (++s_c == NSTAGE) s_c = 0;
    }
    __syncthreads();   // protect smem reuse by epilogues
}

// ---------------- pre-pass kernels ----------------
__global__ __launch_bounds__(256)
void prep_x(const float* __restrict__ x1, const float* __restrict__ x2)
{
    int i = blockIdx.x * 256 + threadIdx.x;
    if (i >= BX * D) return;
    g_x1h[i] = __float2half_rn(x1[i]);
    g_x2h[i] = __float2half_rn(x2[i]);
}

// Transpose 256*W core for o in [o0, o0+64)
__global__ __launch_bounds__(256)
void prep_w(const float* __restrict__ W, int o0)
{
    const int o  = o0 + blockIdx.z;
    const int i0 = blockIdx.y * 64, j0 = blockIdx.x * 32;
    __shared__ float t[64][33];
    const int tid = threadIdx.x;
    const float* Wo = W + (size_t)o * WSTRIDE;

    #pragma unroll
    for (int p = 0; p < 8; p++) {
        int idx = p * 256 + tid;
        int i = idx >> 5, j = idx & 31;
        t[i][j] = Wo[(size_t)(i0 + i) * 513 + (j0 + j)] * WSCALE;
    }
    __syncthreads();

    const size_t ob = (size_t)o * D * D;
    #pragma unroll
    for (int p = 0; p < 4; p++) {
        const int jl = p * 8 + (tid >> 5);
        const int i2 = (tid & 31) * 2;
        const size_t off = ob + (size_t)(j0 + jl) * D + i0 + i2;
        *reinterpret_cast<__half2*>(g_Wh + off) =
            __halves2half2(__float2half_rn(t[i2][jl]), __float2half_rn(t[i2 + 1][jl]));
    }
}

__global__ __launch_bounds__(256)
void comb_w(const float* __restrict__ W, const float* __restrict__ Wlin,
            const float* __restrict__ b_lin, const float* __restrict__ bw)
{
    const int idx = blockIdx.x * 256 + threadIdx.x;
    if (idx >= 2 * O * D) return;
    const float e0 = expf(bw[0]), e1 = expf(bw[1]);
    const float w0 = e0 / (e0 + e1), w1 = e1 / (e0 + e1);

    const int d = idx & 511;
    const int o = (idx >> 9) & 127;
    const int which = idx >> 16;
    const float we = which ? W[(size_t)o * WSTRIDE + (size_t)512 * 513 + d]
                           : W[(size_t)o * WSTRIDE + (size_t)d * 513 + 512];
    const float wl = Wlin[(size_t)(which * D + d) * O + o];
    g_WcH[idx] = __float2half_rn((w0 * we + w1 * wl) * WSCALE);

    if (idx < O)          g_bias[idx] = w1 * b_lin[idx];
    else if (idx < 2 * O) {
        const int oo = idx - O;
        g_bias[idx] = w0 * W[(size_t)oo * WSTRIDE + (size_t)512 * 513 + 512];
    }
}

// A-terms: A{1,2}[m,o] = (x @ Wc^T)/256 + bias
__global__ __launch_bounds__(256, 2)
void A_terms_mma()
{
    extern __shared__ char smem[];
    const uint32_t sb = s2u(smem);
    const int tid = threadIdx.x;
    const int m0 = blockIdx.x * 128;
    const int which = blockIdx.y;

    const __half* Ah = (which ? g_x2h : g_x1h) + (size_t)m0 * D;
    const __half* Bh = g_WcH + (size_t)which * O * D;

    float acc[4][4][4] = {};
    gemm_loop(sb, tid, Ah, Bh, acc);

    float* dst = which ? g_A2 : g_A1;
    const float* bias = g_bias + which * O;
    const int lane = tid & 31;
    const int warp_m = (tid >> 5) & 1, warp_n = tid >> 6;
    #pragma unroll
    for (int mt = 0; mt < 4; mt++)
        #pragma unroll
        for (int nt = 0; nt < 4; nt++) {
            const int oc = warp_n * 32 + nt * 8 + (lane & 3) * 2;
            const float b0 = bias[oc], b1 = bias[oc + 1];
            #pragma unroll
            for (int h = 0; h < 2; h++) {
                const int m = m0 + warp_m * 64 + mt * 16 + (lane >> 2) + h * 8;
                *reinterpret_cast<float2*>(dst + (size_t)m * O + oc) =
                    make_float2(fmaf(acc[mt][nt][h * 2],     INV_WSCALE, b0),
                                fmaf(acc[mt][nt][h * 2 + 1], INV_WSCALE, b1));
            }
        }
}

// ---- stage 1 quadrant: T[m, o, j] for m in [m0b, m0b+512), o in [o0, o0+64)
#define S1_PITCH 272
__global__ __launch_bounds__(256, 2)
void stage1_mma(int o0, int m0b)
{
    extern __shared__ char smem[];
    const uint32_t sb = s2u(smem);
    const int tid = threadIdx.x;
    const int m0 = m0b + blockIdx.x * 128;
    const int o  = o0 + (blockIdx.y >> 2);
    const int j0 = (blockIdx.y & 3) * 128;

    float acc[4][4][4] = {};
    gemm_loop(sb, tid,
              g_x1h + (size_t)m0 * D,
              g_Wh + (size_t)o * D * D + (size_t)j0 * D, acc);

    const int lane = tid & 31;
    const int warp_m = (tid >> 5) & 1, warp_n = tid >> 6;
    #pragma unroll
    for (int mt = 0; mt < 4; mt++)
        #pragma unroll
        for (int nt = 0; nt < 4; nt++)
            #pragma unroll
            for (int h = 0; h < 2; h++) {
                const int ml = warp_m * 64 + mt * 16 + (lane >> 2) + h * 8;
                const int jl = warp_n * 32 + nt * 8 + (lane & 3) * 2;
                *reinterpret_cast<__half2*>(smem + ml * S1_PITCH + jl * 2) =
                    __halves2half2(__float2half_rn(acc[mt][nt][h * 2]),
                                   __float2half_rn(acc[mt][nt][h * 2 + 1]));
            }
    __syncthreads();

    #pragma unroll
    for (int p = 0; p < 8; p++) {
        const int q = p * 256 + tid;
        const int r = q >> 4, c = q & 15;
        const size_t go = ((size_t)(m0 + r) * O + o) * D + j0 + c * 8;
        *reinterpret_cast<uint4*>(g_Th + go) =
            *reinterpret_cast<uint4*>(smem + r * S1_PITCH + c * 16);
    }
}

// ---- stage 2 half: out for bx in [bx0, bx0+512) ----------------------------
#define S2_PITCH 528
__global__ __launch_bounds__(256, 2)
void stage2_mma(const float* __restrict__ bw, float* __restrict__ out, int bx0)
{
    extern __shared__ char smem[];
    const uint32_t sb = s2u(smem);
    const int tid = threadIdx.x;
    const int y0 = blockIdx.x * 128;
    const int bx = bx0 + blockIdx.y;
    const int b  = bx >> 8;
    const size_t arow = (size_t)(b * L + y0) * D;

    float acc[4][4][4] = {};
    gemm_loop(sb, tid,
              g_x2h + arow,
              g_Th + (size_t)bx * O * D, acc);

    const int lane = tid & 31;
    const int warp_m = (tid >> 5) & 1, warp_n = tid >> 6;
    #pragma unroll
    for (int mt = 0; mt < 4; mt++)
        #pragma unroll
        for (int nt = 0; nt < 4; nt++)
            #pragma unroll
            for (int h = 0; h < 2; h++) {
                const int yl = warp_m * 64 + mt * 16 + (lane >> 2) + h * 8;
                const int ol = warp_n * 32 + nt * 8 + (lane & 3) * 2;
                *reinterpret_cast<float2*>(smem + yl * S2_PITCH + ol * 4) =
                    make_float2(acc[mt][nt][h * 2], acc[mt][nt][h * 2 + 1]);
            }
    __syncthreads();

    const float e0 = expf(bw[0]), e1 = expf(bw[1]);
    const float w0s = (e0 / (e0 + e1)) * INV_WSCALE;

    #pragma unroll
    for (int p = 0; p < 16; p++) {
        const int q = p * 256 + tid;
        const int r = q >> 5, c = q & 31;
        const float4 v = *reinterpret_cast<float4*>(smem + r * S2_PITCH + c * 16);
        const float4 a1 = *reinterpret_cast<const float4*>(g_A1 + (size_t)bx * O + c * 4);
        const float4 a2 = *reinterpret_cast<const float4*>(g_A2 + (size_t)(b * L + y0 + r) * O + c * 4);
        float4 rr;
        rr.x = fmaf(w0s, v.x, a1.x + a2.x);
        rr.y = fmaf(w0s, v.y, a1.y + a2.y);
        rr.z = fmaf(w0s, v.z, a1.z + a2.z);
        rr.w = fmaf(w0s, v.w, a1.w + a2.w);
        *reinterpret_cast<float4*>(out + ((size_t)bx * L + y0 + r) * O + c * 4) = rr;
    }
}

// ---------------------------------------------------------------------------
extern "C" void kernel_launch(void* const* d_in, const int* in_sizes, int n_in,
                              void* d_out, int out_size)
{
    const float* x1    = (const float*)d_in[0];
    const float* x2    = (const float*)d_in[1];
    const float* bw    = (const float*)d_in[2];
    const float* W_bil = (const float*)d_in[3];
    const float* W_lin = (const float*)d_in[4];
    const float* b_lin = (const float*)d_in[5];
    float* out = (float*)d_out;

    static cudaStream_t s1 = nullptr, s2 = nullptr, s3 = nullptr;
    static cudaEvent_t evRoot, evX, ev3, evA0, evA1, evB0, evB1;
    if (s1 == nullptr) {
        cudaStreamCreateWithFlags(&s1, cudaStreamNonBlocking);
        cudaStreamCreateWithFlags(&s2, cudaStreamNonBlocking);
        cudaStreamCreateWithFlags(&s3, cudaStreamNonBlocking);
        cudaEventCreateWithFlags(&evRoot, cudaEventDisableTiming);
        cudaEventCreateWithFlags(&evX,    cudaEventDisableTiming);
        cudaEventCreateWithFlags(&ev3,    cudaEventDisableTiming);
        cudaEventCreateWithFlags(&evA0,   cudaEventDisableTiming);
        cudaEventCreateWithFlags(&evA1,   cudaEventDisableTiming);
        cudaEventCreateWithFlags(&evB0,   cudaEventDisableTiming);
        cudaEventCreateWithFlags(&evB1,   cudaEventDisableTiming);
        cudaFuncSetAttribute(A_terms_mma, cudaFuncAttributeMaxDynamicSharedMemorySize, GSMEM);
        cudaFuncSetAttribute(stage1_mma,  cudaFuncAttributeMaxDynamicSharedMemorySize, GSMEM);
        cudaFuncSetAttribute(stage2_mma,  cudaFuncAttributeMaxDynamicSharedMemorySize, GSMEM);
    }

    // Fork side streams from the capture-origin stream.
    cudaEventRecord(evRoot, 0);
    cudaStreamWaitEvent(s1, evRoot, 0);
    cudaStreamWaitEvent(s2, evRoot, 0);
    cudaStreamWaitEvent(s3, evRoot, 0);

    // prep_w halves (depend only on W_bil).
    prep_w<<<dim3(16, 8, 64), 256, 0, s1>>>(W_bil, 0);
    prep_w<<<dim3(16, 8, 64), 256, 0, s2>>>(W_bil, 64);

    // prep_x on origin; feeds stage1 and the A-terms branch.
    prep_x<<<(BX * D + 255) / 256, 256>>>(x1, x2);
    cudaEventRecord(evX, 0);

    // Branch A: comb_w -> A_terms (hidden under prep_w/stage1).
    cudaStreamWaitEvent(s3, evX, 0);
    comb_w<<<(2 * O * D + 255) / 256, 256, 0, s3>>>(W_bil, W_lin, b_lin, bw);
    A_terms_mma<<<dim3(8, 2), 256, GSMEM, s3>>>();
    cudaEventRecord(ev3, s3);

    // stage1 quadrants: s1 handles o<64 (m-half0 then m-half1), s2 handles o>=64.
    cudaStreamWaitEvent(s1, evX, 0);
    stage1_mma<<<dim3(4, 256), 256, GSMEM, s1>>>(0, 0);
    cudaEventRecord(evA0, s1);
    stage1_mma<<<dim3(4, 256), 256, GSMEM, s1>>>(0, 512);
    cudaEventRecord(evA1, s1);

    cudaStreamWaitEvent(s2, evX, 0);
    stage1_mma<<<dim3(4, 256), 256, GSMEM, s2>>>(64, 0);
    cudaEventRecord(evB0, s2);
    stage1_mma<<<dim3(4, 256), 256, GSMEM, s2>>>(64, 512);
    cudaEventRecord(evB1, s2);

    // stage2 halves: half0 starts as soon as m-half0's T (both o halves) + A-terms ready.
    cudaStreamWaitEvent(0, evA0, 0);
    cudaStreamWaitEvent(0, evB0, 0);
    cudaStreamWaitEvent(0, ev3, 0);
    stage2_mma<<<dim3(2, 512), 256, GSMEM>>>(bw, out, 0);

    cudaStreamWaitEvent(0, evA1, 0);
    cudaStreamWaitEvent(0, evB1, 0);
    stage2_mma<<<dim3(2, 512), 256, GSMEM>>>(bw, out, 512);
}